// round 5
// baseline (speedup 1.0000x reference)
#include <cuda_runtime.h>
#include <cuda_bf16.h>
#include <math.h>
#include <stdint.h>

#define LAYERS 8
#define HDIM   1024
#define KDIM   1024
#define IDIM   4096
#define VOCAB  32000
#define BATCH  2
#define SEQ    2048
#define MTOK   (BATCH * SEQ)

typedef __nv_bfloat16 bf16;
typedef __nv_bfloat162 bf162;

// ---------------- scratch (device globals) ----------------
__device__ float g_x[(long)MTOK * HDIM];
__device__ float g_qkv[(long)MTOK * 3 * KDIM];
__device__ float g_scores[(long)BATCH * SEQ * SEQ];
__device__ bf16 g_xh[(long)MTOK * HDIM],      g_xl[(long)MTOK * HDIM];
__device__ bf16 g_qkvh[(long)MTOK * 3 * KDIM], g_qkvl[(long)MTOK * 3 * KDIM];
__device__ bf16 g_sh[(long)BATCH * SEQ * SEQ], g_sl[(long)BATCH * SEQ * SEQ];
__device__ bf16 g_vTh[(long)BATCH * KDIM * SEQ], g_vTl[(long)BATCH * KDIM * SEQ];
__device__ bf16 g_oh[(long)MTOK * KDIM],      g_ol[(long)MTOK * KDIM];
__device__ bf16 g_hh[(long)MTOK * IDIM],      g_hl[(long)MTOK * IDIM];
__device__ bf16 g_qkvTh[(long)LAYERS * 3 * KDIM * HDIM], g_qkvTl[(long)LAYERS * 3 * KDIM * HDIM];
__device__ bf16 g_oTh[(long)LAYERS * HDIM * KDIM],       g_oTl[(long)LAYERS * HDIM * KDIM];
__device__ bf16 g_upTh[(long)LAYERS * IDIM * HDIM],      g_upTl[(long)LAYERS * IDIM * HDIM];
__device__ bf16 g_dnTh[(long)LAYERS * HDIM * IDIM],      g_dnTl[(long)LAYERS * HDIM * IDIM];
__device__ bf16 g_unTh[(long)VOCAB * HDIM],              g_unTl[(long)VOCAB * HDIM];

// ---------------- helpers ----------------
__device__ __forceinline__ uint32_t smem_u32(const void* p) {
    uint32_t a;
    asm("{ .reg .u64 t; cvta.to.shared.u64 t, %1; cvt.u32.u64 %0, t; }" : "=r"(a) : "l"(p));
    return a;
}
__device__ __forceinline__ void split1(float v, bf16& h, bf16& l) {
    h = __float2bfloat16_rn(v);
    l = __float2bfloat16_rn(v - __bfloat162float(h));
}

#define CP_ASYNC16(dst, src) \
    asm volatile("cp.async.cg.shared.global [%0], [%1], 16;" :: "r"(dst), "l"(src) : "memory")
#define CP_COMMIT() asm volatile("cp.async.commit_group;" ::: "memory")
#define CP_WAIT1()  asm volatile("cp.async.wait_group 1;" ::: "memory")

#define LDSM_X4(r, a)                                                        \
    asm volatile("ldmatrix.sync.aligned.m8n8.x4.shared.b16 {%0,%1,%2,%3}, [%4];" \
        : "=r"((r)[0]), "=r"((r)[1]), "=r"((r)[2]), "=r"((r)[3]) : "r"(a))

__device__ __forceinline__ void mma_bf16(float* c, const uint32_t* a,
                                         uint32_t b0, uint32_t b1) {
    asm volatile(
        "mma.sync.aligned.m16n8k16.row.col.f32.bf16.bf16.f32 "
        "{%0,%1,%2,%3}, {%4,%5,%6,%7}, {%8,%9}, {%0,%1,%2,%3};"
        : "+f"(c[0]), "+f"(c[1]), "+f"(c[2]), "+f"(c[3])
        : "r"(a[0]), "r"(a[1]), "r"(a[2]), "r"(a[3]), "r"(b0), "r"(b1));
}

// ---------------- embed (+split) ----------------
__global__ void embed_split(const int* __restrict__ tokens, const float* __restrict__ emb,
                            float* __restrict__ x, bf16* __restrict__ xh, bf16* __restrict__ xl) {
    int i = blockIdx.x;
    int tok = tokens[i];
    const float4* src = (const float4*)(emb + (long)tok * HDIM);
    float4* dst = (float4*)(x + (long)i * HDIM);
    for (int c = threadIdx.x; c < HDIM / 4; c += blockDim.x) {
        float4 v = src[c];
        dst[c] = v;
        bf16 h0, l0, h1, l1, h2, l2, h3, l3;
        split1(v.x, h0, l0); split1(v.y, h1, l1);
        split1(v.z, h2, l2); split1(v.w, h3, l3);
        long base = (long)i * HDIM + c * 4;
        bf162 a; a.x = h0; a.y = h1;
        bf162 b; b.x = h2; b.y = h3;
        *(bf162*)(xh + base) = a; *(bf162*)(xh + base + 2) = b;
        a.x = l0; a.y = l1; b.x = l2; b.y = l3;
        *(bf162*)(xl + base) = a; *(bf162*)(xl + base + 2) = b;
    }
}

// ---------------- transpose + split ----------------
__global__ void transpose_split(const float* __restrict__ src,
                                bf16* __restrict__ dh, bf16* __restrict__ dl,
                                int R, int lds, long sbatch, long dbatch) {
    __shared__ float t[32][33];
    src += (long)blockIdx.z * sbatch;
    dh  += (long)blockIdx.z * dbatch;
    dl  += (long)blockIdx.z * dbatch;
    int c0 = blockIdx.x << 5, r0 = blockIdx.y << 5;
    int x = threadIdx.x, y = threadIdx.y;
    #pragma unroll
    for (int i = y; i < 32; i += 8)
        t[i][x] = src[(long)(r0 + i) * lds + c0 + x];
    __syncthreads();
    #pragma unroll
    for (int j = y; j < 32; j += 8) {
        float v = t[x][j];
        bf16 h, l; split1(v, h, l);
        long idx = (long)(c0 + j) * R + r0 + x;
        dh[idx] = h; dl[idx] = l;
    }
}

// ---------------- causal softmax -> split bf16 ----------------
__global__ void softmax_split(float* __restrict__ sc, bf16* __restrict__ sh,
                              bf16* __restrict__ sl, float scale) {
    int row = blockIdx.x;
    int s = row & (SEQ - 1);
    float* p = sc + (long)row * SEQ;
    bf16* ph = sh + (long)row * SEQ;
    bf16* pl = sl + (long)row * SEQ;
    int tid = threadIdx.x;
    __shared__ float red[256];

    float m = -INFINITY;
    for (int t = tid; t <= s; t += blockDim.x) m = fmaxf(m, p[t] * scale);
    red[tid] = m; __syncthreads();
    for (int o = 128; o > 0; o >>= 1) {
        if (tid < o) red[tid] = fmaxf(red[tid], red[tid + o]);
        __syncthreads();
    }
    m = red[0]; __syncthreads();

    float sum = 0.f;
    for (int t = tid; t <= s; t += blockDim.x) {
        float e = __expf(p[t] * scale - m);
        p[t] = e;
        sum += e;
    }
    red[tid] = sum; __syncthreads();
    for (int o = 128; o > 0; o >>= 1) {
        if (tid < o) red[tid] += red[tid + o];
        __syncthreads();
    }
    float inv = 1.f / red[0];
    const bf16 z = __float2bfloat16(0.f);
    for (int t = tid; t <= s; t += blockDim.x) {
        bf16 h, l; split1(p[t] * inv, h, l);
        ph[t] = h; pl[t] = l;
    }
    for (int t = s + 1 + tid; t < SEQ; t += blockDim.x) { ph[t] = z; pl[t] = z; }
}

// ---------------- HMMA GEMM: C[M,N] = A[M,K] @ B[N,K]^T ----------------
// 512 threads, 16 warps (4x4), 32x32 warp tiles; 128x128x32 CTA tile.
// 3-pass hi/lo split: Ah*Bh + Ah*Bl + Al*Bh.
// EPI: 0 none, 1 +=Cf, 2 relu(+bias), 3 +bias+Cf, 4 +bias
// CSKIP: skip blocks with n0 > m0+127 (causal scores)
// CK: truncate K loop at m0+128 (attn@V with causal attn matrix)
#define DEPTH     3
#define MAT_BYTES 10240          // 128 rows * 80B
#define STG_BYTES (4 * MAT_BYTES)
#define SMEM_TOT  (DEPTH * STG_BYTES)

template<int EPI, bool F32OUT, bool SPLITOUT, bool CSKIP, bool CK>
__global__ __launch_bounds__(512, 1)
void mma_gemm(const bf16* __restrict__ Ah, const bf16* __restrict__ Al,
              const bf16* __restrict__ Bh, const bf16* __restrict__ Bl,
              float* __restrict__ Cf, bf16* __restrict__ Ch, bf16* __restrict__ Cl,
              const float* __restrict__ bias,
              int K, int lda, int ldb, int ldc,
              long bsA, long bsB, long bsC) {
    const int m0 = blockIdx.y << 7, n0 = blockIdx.x << 7;
    if (CSKIP && n0 > m0 + 127) return;

    const long zA = (long)blockIdx.z * bsA;
    const long zB = (long)blockIdx.z * bsB;
    const long zC = (long)blockIdx.z * bsC;

    extern __shared__ char smem[];
    const uint32_t sbase = smem_u32(smem);
    const int tid = threadIdx.x;
    const int lane = tid & 31, wid = tid >> 5;
    const int wm = wid & 3, wn = wid >> 2;        // 4x4 warp grid
    int NK = K >> 5;
    if (CK) { int nke = (m0 + 128) >> 5; NK = (nke < NK) ? nke : NK; }

    const bf16* gm[4] = { Ah + zA + (long)m0 * lda, Al + zA + (long)m0 * lda,
                          Bh + zB + (long)n0 * ldb, Bl + zB + (long)n0 * ldb };
    const int ldm[4]  = { lda, lda, ldb, ldb };
    const int row_lo = tid >> 2;     // 0..127
    const int atom   = tid & 3;      // 16B chunk in 32-col row

    float acc[2][4][4];
    #pragma unroll
    for (int a = 0; a < 2; a++)
        #pragma unroll
        for (int b = 0; b < 4; b++)
            #pragma unroll
            for (int c = 0; c < 4; c++) acc[a][b][c] = 0.f;

    #define LOAD_STAGE(kt, slot) do {                                          \
        uint32_t st_ = sbase + (slot) * STG_BYTES;                             \
        _Pragma("unroll")                                                      \
        for (int mat = 0; mat < 4; mat++) {                                    \
            const bf16* g = gm[mat] + (long)row_lo * ldm[mat] + ((kt) << 5) + (atom << 3); \
            CP_ASYNC16(st_ + mat * MAT_BYTES + row_lo * 80 + (atom << 4), g);  \
        }                                                                      \
        CP_COMMIT();                                                           \
    } while (0)

    LOAD_STAGE(0, 0);
    LOAD_STAGE(1, 1);

    for (int kt = 0; kt < NK; kt++) {
        CP_WAIT1();
        __syncthreads();
        if (kt + 2 < NK) { LOAD_STAGE(kt + 2, (kt + 2) % DEPTH); }
        else             { CP_COMMIT(); }

        uint32_t st = sbase + (kt % DEPTH) * STG_BYTES;
        #pragma unroll
        for (int s = 0; s < 2; s++) {
            uint32_t a_h[2][4], a_l[2][4], b_h[2][4], b_l[2][4];
            #pragma unroll
            for (int mt = 0; mt < 2; mt++) {
                uint32_t ad = st + (uint32_t)(wm * 32 + mt * 16 + (lane & 15)) * 80
                              + s * 32 + ((lane >> 4) << 4);
                LDSM_X4(a_h[mt], ad);
                LDSM_X4(a_l[mt], ad + MAT_BYTES);
            }
            #pragma unroll
            for (int p = 0; p < 2; p++) {
                uint32_t bd = st + 2 * MAT_BYTES
                              + (uint32_t)(wn * 32 + p * 16 + ((lane >> 4) << 3) + (lane & 7)) * 80
                              + s * 32 + (((lane >> 3) & 1) << 4);
                LDSM_X4(b_h[p], bd);
                LDSM_X4(b_l[p], bd + MAT_BYTES);
            }
            #pragma unroll
            for (int mt = 0; mt < 2; mt++)
                #pragma unroll
                for (int nt = 0; nt < 4; nt++) {
                    uint32_t bh0 = b_h[nt >> 1][(nt & 1) * 2];
                    uint32_t bh1 = b_h[nt >> 1][(nt & 1) * 2 + 1];
                    uint32_t bl0 = b_l[nt >> 1][(nt & 1) * 2];
                    uint32_t bl1 = b_l[nt >> 1][(nt & 1) * 2 + 1];
                    mma_bf16(acc[mt][nt], a_h[mt], bh0, bh1);
                    mma_bf16(acc[mt][nt], a_h[mt], bl0, bl1);
                    mma_bf16(acc[mt][nt], a_l[mt], bh0, bh1);
                }
        }
    }

    // ---- epilogue ----
    #pragma unroll
    for (int mt = 0; mt < 2; mt++) {
        #pragma unroll
        for (int nt = 0; nt < 4; nt++) {
            int mbase = m0 + wm * 32 + mt * 16 + (lane >> 2);
            int n = n0 + wn * 32 + nt * 8 + (lane & 3) * 2;
            #pragma unroll
            for (int hf = 0; hf < 2; hf++) {
                int mm = mbase + hf * 8;
                float vx = acc[mt][nt][hf * 2 + 0];
                float vy = acc[mt][nt][hf * 2 + 1];
                long idx = zC + (long)mm * ldc + n;
                if (EPI >= 2) { vx += bias[n]; vy += bias[n + 1]; }
                if (EPI == 2) { vx = fmaxf(vx, 0.f); vy = fmaxf(vy, 0.f); }
                if (EPI == 1 || EPI == 3) {
                    float2 old = *(const float2*)(Cf + idx);
                    vx += old.x; vy += old.y;
                }
                if (F32OUT) {
                    float2 o; o.x = vx; o.y = vy;
                    *(float2*)(Cf + idx) = o;
                }
                if (SPLITOUT) {
                    bf16 hx, lx, hy, ly;
                    split1(vx, hx, lx); split1(vy, hy, ly);
                    bf162 hv; hv.x = hx; hv.y = hy;
                    bf162 lv; lv.x = lx; lv.y = ly;
                    *(bf162*)(Ch + idx) = hv;
                    *(bf162*)(Cl + idx) = lv;
                }
            }
        }
    }
}

// ---------------- host ----------------
template<int EPI, bool F32O, bool SPL, bool CSKIP = false, bool CK = false>
static void launch_mma(dim3 grid, const bf16* Ah, const bf16* Al,
                       const bf16* Bh, const bf16* Bl,
                       float* Cf, bf16* Ch, bf16* Cl, const float* bias,
                       int K, int lda, int ldb, int ldc,
                       long bsA = 0, long bsB = 0, long bsC = 0) {
    cudaFuncSetAttribute(mma_gemm<EPI, F32O, SPL, CSKIP, CK>,
                         cudaFuncAttributeMaxDynamicSharedMemorySize, SMEM_TOT);
    mma_gemm<EPI, F32O, SPL, CSKIP, CK><<<grid, 512, SMEM_TOT>>>(
        Ah, Al, Bh, Bl, Cf, Ch, Cl, bias, K, lda, ldb, ldc, bsA, bsB, bsC);
}

extern "C" void kernel_launch(void* const* d_in, const int* in_sizes, int n_in,
                              void* d_out, int out_size) {
    const int*   tokens    = (const int*)  d_in[0];
    const float* embedding = (const float*)d_in[1];
    const float* qkv_w     = (const float*)d_in[2];
    const float* o_w       = (const float*)d_in[3];
    const float* up_w      = (const float*)d_in[4];
    const float* up_b      = (const float*)d_in[5];
    const float* down_w    = (const float*)d_in[6];
    const float* down_b    = (const float*)d_in[7];
    const float* unemb_w   = (const float*)d_in[8];
    const float* unemb_b   = (const float*)d_in[9];
    float* logits = (float*)d_out;

    float *x, *qkv, *sc;
    bf16 *xh, *xl, *qh, *ql, *sh, *sl, *vTh, *vTl, *oh, *ol, *hh, *hl;
    bf16 *qkvTh, *qkvTl, *oTh, *oTl, *upTh, *upTl, *dnTh, *dnTl, *unTh, *unTl;
    cudaGetSymbolAddress((void**)&x, g_x);
    cudaGetSymbolAddress((void**)&qkv, g_qkv);
    cudaGetSymbolAddress((void**)&sc, g_scores);
    cudaGetSymbolAddress((void**)&xh, g_xh);   cudaGetSymbolAddress((void**)&xl, g_xl);
    cudaGetSymbolAddress((void**)&qh, g_qkvh); cudaGetSymbolAddress((void**)&ql, g_qkvl);
    cudaGetSymbolAddress((void**)&sh, g_sh);   cudaGetSymbolAddress((void**)&sl, g_sl);
    cudaGetSymbolAddress((void**)&vTh, g_vTh); cudaGetSymbolAddress((void**)&vTl, g_vTl);
    cudaGetSymbolAddress((void**)&oh, g_oh);   cudaGetSymbolAddress((void**)&ol, g_ol);
    cudaGetSymbolAddress((void**)&hh, g_hh);   cudaGetSymbolAddress((void**)&hl, g_hl);
    cudaGetSymbolAddress((void**)&qkvTh, g_qkvTh); cudaGetSymbolAddress((void**)&qkvTl, g_qkvTl);
    cudaGetSymbolAddress((void**)&oTh, g_oTh);     cudaGetSymbolAddress((void**)&oTl, g_oTl);
    cudaGetSymbolAddress((void**)&upTh, g_upTh);   cudaGetSymbolAddress((void**)&upTl, g_upTl);
    cudaGetSymbolAddress((void**)&dnTh, g_dnTh);   cudaGetSymbolAddress((void**)&dnTl, g_dnTl);
    cudaGetSymbolAddress((void**)&unTh, g_unTh);   cudaGetSymbolAddress((void**)&unTl, g_unTl);

    const float scale = 1.0f / sqrtf((float)KDIM);
    dim3 tb(32, 8);

    transpose_split<<<dim3(3 * KDIM / 32, HDIM / 32, LAYERS), tb>>>(
        qkv_w, qkvTh, qkvTl, HDIM, 3 * KDIM, (long)HDIM * 3 * KDIM, (long)HDIM * 3 * KDIM);
    transpose_split<<<dim3(HDIM / 32, KDIM / 32, LAYERS), tb>>>(
        o_w, oTh, oTl, KDIM, HDIM, (long)KDIM * HDIM, (long)KDIM * HDIM);
    transpose_split<<<dim3(IDIM / 32, HDIM / 32, LAYERS), tb>>>(
        up_w, upTh, upTl, HDIM, IDIM, (long)HDIM * IDIM, (long)HDIM * IDIM);
    transpose_split<<<dim3(HDIM / 32, IDIM / 32, LAYERS), tb>>>(
        down_w, dnTh, dnTl, IDIM, HDIM, (long)IDIM * HDIM, (long)IDIM * HDIM);
    transpose_split<<<dim3(VOCAB / 32, HDIM / 32, 1), tb>>>(
        unemb_w, unTh, unTl, HDIM, VOCAB, 0, 0);

    embed_split<<<MTOK, 256>>>(tokens, embedding, x, xh, xl);

    for (int l = 0; l < LAYERS; l++) {
        bf16* wqh = qkvTh + (long)l * 3 * KDIM * HDIM;
        bf16* wql = qkvTl + (long)l * 3 * KDIM * HDIM;
        bf16* woh = oTh   + (long)l * HDIM * KDIM;
        bf16* wol = oTl   + (long)l * HDIM * KDIM;
        bf16* wuh = upTh  + (long)l * IDIM * HDIM;
        bf16* wul = upTl  + (long)l * IDIM * HDIM;
        bf16* wdh = dnTh  + (long)l * HDIM * IDIM;
        bf16* wdl = dnTl  + (long)l * HDIM * IDIM;
        const float* bu = up_b   + (long)l * IDIM;
        const float* bd = down_b + (long)l * HDIM;

        // qkv = x @ Wqkv -> fp32 (for V transpose) + split
        launch_mma<0, true, true>(dim3(3 * KDIM / 128, MTOK / 128, 1),
            xh, xl, wqh, wql, qkv, qh, ql, nullptr, HDIM, HDIM, HDIM, 3 * KDIM);

        transpose_split<<<dim3(KDIM / 32, SEQ / 32, BATCH), tb>>>(
            qkv + 2 * KDIM, vTh, vTl, SEQ, 3 * KDIM,
            (long)SEQ * 3 * KDIM, (long)KDIM * SEQ);

        // scores = Q @ K^T per batch (skip upper-triangle blocks)
        launch_mma<0, true, false, true, false>(dim3(SEQ / 128, SEQ / 128, BATCH),
            qh, ql, qh + KDIM, ql + KDIM, sc, nullptr, nullptr, nullptr,
            KDIM, 3 * KDIM, 3 * KDIM, SEQ,
            (long)SEQ * 3 * KDIM, (long)SEQ * 3 * KDIM, (long)SEQ * SEQ);

        softmax_split<<<BATCH * SEQ, 256>>>(sc, sh, sl, scale);

        // o = attn @ V per batch (K loop truncated at diagonal)
        launch_mma<0, false, true, false, true>(dim3(KDIM / 128, SEQ / 128, BATCH),
            sh, sl, vTh, vTl, nullptr, oh, ol, nullptr,
            SEQ, SEQ, SEQ, KDIM,
            (long)SEQ * SEQ, (long)KDIM * SEQ, (long)SEQ * KDIM);

        // x += o @ Wo
        launch_mma<1, true, true>(dim3(HDIM / 128, MTOK / 128, 1),
            oh, ol, woh, wol, x, xh, xl, nullptr, KDIM, KDIM, KDIM, HDIM);

        // h = relu(x @ Wu + bu)
        launch_mma<2, false, true>(dim3(IDIM / 128, MTOK / 128, 1),
            xh, xl, wuh, wul, nullptr, hh, hl, bu, HDIM, HDIM, HDIM, IDIM);

        // x += h @ Wd + bd
        launch_mma<3, true, true>(dim3(HDIM / 128, MTOK / 128, 1),
            hh, hl, wdh, wdl, x, xh, xl, bd, IDIM, IDIM, IDIM, HDIM);
    }

    launch_mma<4, true, false>(dim3(VOCAB / 128, MTOK / 128, 1),
        xh, xl, unTh, unTl, logits, nullptr, nullptr, unemb_b,
        HDIM, HDIM, HDIM, VOCAB);
}

// round 6
// speedup vs baseline: 1.6024x; 1.6024x over previous
#include <cuda_runtime.h>
#include <cuda_bf16.h>
#include <cuda_fp16.h>
#include <math.h>
#include <stdint.h>

#define LAYERS 8
#define HDIM   1024
#define KDIM   1024
#define IDIM   4096
#define VOCAB  32000
#define BATCH  2
#define SEQ    2048
#define MTOK   (BATCH * SEQ)

typedef __nv_bfloat16 bf16;
typedef __nv_bfloat162 bf162;

// ---------------- scratch (device globals) ----------------
__device__ float g_x[(long)MTOK * HDIM];
__device__ float g_qkv[(long)MTOK * 3 * KDIM];
__device__ float g_scores[(long)BATCH * SEQ * SEQ];
__device__ bf16 g_xh[(long)MTOK * HDIM],      g_xl[(long)MTOK * HDIM];
__device__ bf16 g_qkvh[(long)MTOK * 3 * KDIM], g_qkvl[(long)MTOK * 3 * KDIM];
__device__ bf16 g_sh[(long)BATCH * SEQ * SEQ], g_sl[(long)BATCH * SEQ * SEQ];
__device__ bf16 g_vTh[(long)BATCH * KDIM * SEQ], g_vTl[(long)BATCH * KDIM * SEQ];
__device__ bf16 g_oh[(long)MTOK * KDIM],      g_ol[(long)MTOK * KDIM];
__device__ bf16 g_hh[(long)MTOK * IDIM],      g_hl[(long)MTOK * IDIM];
__device__ bf16 g_qkvTh[(long)LAYERS * 3 * KDIM * HDIM], g_qkvTl[(long)LAYERS * 3 * KDIM * HDIM];
__device__ bf16 g_oTh[(long)LAYERS * HDIM * KDIM],       g_oTl[(long)LAYERS * HDIM * KDIM];
__device__ bf16 g_upTh[(long)LAYERS * IDIM * HDIM],      g_upTl[(long)LAYERS * IDIM * HDIM];
__device__ bf16 g_dnTh[(long)LAYERS * HDIM * IDIM],      g_dnTl[(long)LAYERS * HDIM * IDIM];
// fp16 unembed path
__device__ __half g_unT16[(long)VOCAB * HDIM];
__device__ __half g_xh16[(long)MTOK * HDIM], g_xl16[(long)MTOK * HDIM];

// ---------------- helpers ----------------
__device__ __forceinline__ uint32_t smem_u32(const void* p) {
    uint32_t a;
    asm("{ .reg .u64 t; cvta.to.shared.u64 t, %1; cvt.u32.u64 %0, t; }" : "=r"(a) : "l"(p));
    return a;
}
__device__ __forceinline__ void split1(float v, bf16& h, bf16& l) {
    h = __float2bfloat16_rn(v);
    l = __float2bfloat16_rn(v - __bfloat162float(h));
}

#define CP_ASYNC16(dst, src) \
    asm volatile("cp.async.cg.shared.global [%0], [%1], 16;" :: "r"(dst), "l"(src) : "memory")
#define CP_COMMIT() asm volatile("cp.async.commit_group;" ::: "memory")
#define CP_WAIT1()  asm volatile("cp.async.wait_group 1;" ::: "memory")

#define LDSM_X4(r, a)                                                        \
    asm volatile("ldmatrix.sync.aligned.m8n8.x4.shared.b16 {%0,%1,%2,%3}, [%4];" \
        : "=r"((r)[0]), "=r"((r)[1]), "=r"((r)[2]), "=r"((r)[3]) : "r"(a))

template<bool FP16>
__device__ __forceinline__ void mma16(float* c, const uint32_t* a,
                                      uint32_t b0, uint32_t b1) {
    if (FP16)
        asm volatile(
            "mma.sync.aligned.m16n8k16.row.col.f32.f16.f16.f32 "
            "{%0,%1,%2,%3}, {%4,%5,%6,%7}, {%8,%9}, {%0,%1,%2,%3};"
            : "+f"(c[0]), "+f"(c[1]), "+f"(c[2]), "+f"(c[3])
            : "r"(a[0]), "r"(a[1]), "r"(a[2]), "r"(a[3]), "r"(b0), "r"(b1));
    else
        asm volatile(
            "mma.sync.aligned.m16n8k16.row.col.f32.bf16.bf16.f32 "
            "{%0,%1,%2,%3}, {%4,%5,%6,%7}, {%8,%9}, {%0,%1,%2,%3};"
            : "+f"(c[0]), "+f"(c[1]), "+f"(c[2]), "+f"(c[3])
            : "r"(a[0]), "r"(a[1]), "r"(a[2]), "r"(a[3]), "r"(b0), "r"(b1));
}

// ---------------- embed (+split) ----------------
__global__ void embed_split(const int* __restrict__ tokens, const float* __restrict__ emb,
                            float* __restrict__ x, bf16* __restrict__ xh, bf16* __restrict__ xl) {
    int i = blockIdx.x;
    int tok = tokens[i];
    const float4* src = (const float4*)(emb + (long)tok * HDIM);
    float4* dst = (float4*)(x + (long)i * HDIM);
    for (int c = threadIdx.x; c < HDIM / 4; c += blockDim.x) {
        float4 v = src[c];
        dst[c] = v;
        bf16 h0, l0, h1, l1, h2, l2, h3, l3;
        split1(v.x, h0, l0); split1(v.y, h1, l1);
        split1(v.z, h2, l2); split1(v.w, h3, l3);
        long base = (long)i * HDIM + c * 4;
        bf162 a; a.x = h0; a.y = h1;
        bf162 b; b.x = h2; b.y = h3;
        *(bf162*)(xh + base) = a; *(bf162*)(xh + base + 2) = b;
        a.x = l0; a.y = l1; b.x = l2; b.y = l3;
        *(bf162*)(xl + base) = a; *(bf162*)(xl + base + 2) = b;
    }
}

// ---------------- transpose + split (bf16 hi/lo) ----------------
__global__ void transpose_split(const float* __restrict__ src,
                                bf16* __restrict__ dh, bf16* __restrict__ dl,
                                int R, int lds, long sbatch, long dbatch) {
    __shared__ float t[32][33];
    src += (long)blockIdx.z * sbatch;
    dh  += (long)blockIdx.z * dbatch;
    dl  += (long)blockIdx.z * dbatch;
    int c0 = blockIdx.x << 5, r0 = blockIdx.y << 5;
    int x = threadIdx.x, y = threadIdx.y;
    #pragma unroll
    for (int i = y; i < 32; i += 8)
        t[i][x] = src[(long)(r0 + i) * lds + c0 + x];
    __syncthreads();
    #pragma unroll
    for (int j = y; j < 32; j += 8) {
        float v = t[x][j];
        bf16 h, l; split1(v, h, l);
        long idx = (long)(c0 + j) * R + r0 + x;
        dh[idx] = h; dl[idx] = l;
    }
}

// ---------------- transpose -> single fp16 ----------------
__global__ void transpose_f16(const float* __restrict__ src, __half* __restrict__ dst,
                              int R, int lds) {
    __shared__ float t[32][33];
    int c0 = blockIdx.x << 5, r0 = blockIdx.y << 5;
    int x = threadIdx.x, y = threadIdx.y;
    #pragma unroll
    for (int i = y; i < 32; i += 8)
        t[i][x] = src[(long)(r0 + i) * lds + c0 + x];
    __syncthreads();
    #pragma unroll
    for (int j = y; j < 32; j += 8)
        dst[(long)(c0 + j) * R + r0 + x] = __float2half_rn(t[x][j]);
}

// ---------------- fp32 -> fp16 hi/lo split ----------------
__global__ void split_f16(const float* __restrict__ src,
                          __half* __restrict__ dh, __half* __restrict__ dl) {
    int i = blockIdx.x;
    const float4* s = (const float4*)(src + (long)i * HDIM);
    for (int c = threadIdx.x; c < HDIM / 4; c += blockDim.x) {
        float4 v = s[c];
        long base = (long)i * HDIM + c * 4;
        float vv[4] = { v.x, v.y, v.z, v.w };
        #pragma unroll
        for (int q = 0; q < 4; q++) {
            __half h = __float2half_rn(vv[q]);
            __half l = __float2half_rn(vv[q] - __half2float(h));
            dh[base + q] = h; dl[base + q] = l;
        }
    }
}

// ---------------- causal softmax -> split bf16 ----------------
__global__ void softmax_split(float* __restrict__ sc, bf16* __restrict__ sh,
                              bf16* __restrict__ sl, float scale) {
    int row = blockIdx.x;
    int s = row & (SEQ - 1);
    float* p = sc + (long)row * SEQ;
    bf16* ph = sh + (long)row * SEQ;
    bf16* pl = sl + (long)row * SEQ;
    int tid = threadIdx.x;
    __shared__ float red[256];

    float m = -INFINITY;
    for (int t = tid; t <= s; t += blockDim.x) m = fmaxf(m, p[t] * scale);
    red[tid] = m; __syncthreads();
    for (int o = 128; o > 0; o >>= 1) {
        if (tid < o) red[tid] = fmaxf(red[tid], red[tid + o]);
        __syncthreads();
    }
    m = red[0]; __syncthreads();

    float sum = 0.f;
    for (int t = tid; t <= s; t += blockDim.x) {
        float e = __expf(p[t] * scale - m);
        p[t] = e;
        sum += e;
    }
    red[tid] = sum; __syncthreads();
    for (int o = 128; o > 0; o >>= 1) {
        if (tid < o) red[tid] += red[tid + o];
        __syncthreads();
    }
    float inv = 1.f / red[0];
    const bf16 z = __float2bfloat16(0.f);
    for (int t = tid; t <= s; t += blockDim.x) {
        bf16 h, l; split1(p[t] * inv, h, l);
        ph[t] = h; pl[t] = l;
    }
    for (int t = s + 1 + tid; t < SEQ; t += blockDim.x) { ph[t] = z; pl[t] = z; }
}

// ---------------- HMMA GEMM (R4 config): C[M,N] = A[M,K] @ B[N,K]^T --------
// 256 threads, 8 warps (2x4), 64x32 warp tiles, 128x128x32 CTA tile.
// PASSES=3: Ah*Bh + Ah*Bl + Al*Bh (bf16 split). PASSES=2: Ah*Bh + Al*Bh (B single).
// EPI: 0 none, 1 +=Cf, 2 relu(+bias), 3 +bias+Cf, 4 +bias
// CSKIP: skip blocks with n0 > m0+127.  CK: truncate K loop at m0+128.
#define DEPTH     3
#define MAT_BYTES 10240          // 128 rows * 80B
#define STG_BYTES (4 * MAT_BYTES)
#define SMEM_TOT  (DEPTH * STG_BYTES)

template<int EPI, bool F32OUT, bool SPLITOUT, bool CSKIP, bool CK, int PASSES, bool FP16>
__global__ __launch_bounds__(256, 1)
void mma_gemm(const bf16* __restrict__ Ah, const bf16* __restrict__ Al,
              const bf16* __restrict__ Bh, const bf16* __restrict__ Bl,
              float* __restrict__ Cf, bf16* __restrict__ Ch, bf16* __restrict__ Cl,
              const float* __restrict__ bias,
              int K, int lda, int ldb, int ldc,
              long bsA, long bsB, long bsC) {
    const int m0 = blockIdx.y << 7, n0 = blockIdx.x << 7;
    if (CSKIP && n0 > m0 + 127) return;

    const long zA = (long)blockIdx.z * bsA;
    const long zB = (long)blockIdx.z * bsB;
    const long zC = (long)blockIdx.z * bsC;

    extern __shared__ char smem[];
    const uint32_t sbase = smem_u32(smem);
    const int tid = threadIdx.x;
    const int lane = tid & 31, wid = tid >> 5;
    const int wm = wid & 1, wn = wid >> 1;
    int NK = K >> 5;
    if (CK) { int nke = (m0 + 128) >> 5; NK = (nke < NK) ? nke : NK; }
    constexpr int NMAT = (PASSES == 3) ? 4 : 3;

    const bf16* gm[4] = { Ah + zA + (long)m0 * lda, Al + zA + (long)m0 * lda,
                          Bh + zB + (long)n0 * ldb, Bl + zB + (long)n0 * ldb };
    const int ldm[4]  = { lda, lda, ldb, ldb };
    const int row_lo = tid >> 2;     // 0..63
    const int atom   = tid & 3;

    float acc[4][4][4];
    #pragma unroll
    for (int a = 0; a < 4; a++)
        #pragma unroll
        for (int b = 0; b < 4; b++)
            #pragma unroll
            for (int c = 0; c < 4; c++) acc[a][b][c] = 0.f;

    #define LOAD_STAGE(kt, slot) do {                                          \
        uint32_t st_ = sbase + (slot) * STG_BYTES;                             \
        _Pragma("unroll")                                                      \
        for (int i = 0; i < 2 * NMAT; i++) {                                   \
            int mat = i >> 1;                                                  \
            int row = ((i & 1) << 6) + row_lo;                                 \
            const bf16* g = gm[mat] + (long)row * ldm[mat] + ((kt) << 5) + (atom << 3); \
            CP_ASYNC16(st_ + mat * MAT_BYTES + row * 80 + (atom << 4), g);     \
        }                                                                      \
        CP_COMMIT();                                                           \
    } while (0)

    LOAD_STAGE(0, 0);
    LOAD_STAGE(1, 1);

    for (int kt = 0; kt < NK; kt++) {
        CP_WAIT1();
        __syncthreads();
        if (kt + 2 < NK) { LOAD_STAGE(kt + 2, (kt + 2) % DEPTH); }
        else             { CP_COMMIT(); }

        uint32_t st = sbase + (kt % DEPTH) * STG_BYTES;
        #pragma unroll
        for (int s = 0; s < 2; s++) {
            uint32_t a_h[4][4], a_l[4][4], b_h[2][4], b_l[2][4];
            #pragma unroll
            for (int mt = 0; mt < 4; mt++) {
                uint32_t ad = st + (uint32_t)(wm * 64 + mt * 16 + (lane & 15)) * 80
                              + s * 32 + ((lane >> 4) << 4);
                LDSM_X4(a_h[mt], ad);
                LDSM_X4(a_l[mt], ad + MAT_BYTES);
            }
            #pragma unroll
            for (int p = 0; p < 2; p++) {
                uint32_t bd = st + 2 * MAT_BYTES
                              + (uint32_t)(wn * 32 + p * 16 + ((lane >> 4) << 3) + (lane & 7)) * 80
                              + s * 32 + (((lane >> 3) & 1) << 4);
                LDSM_X4(b_h[p], bd);
                if (PASSES == 3) LDSM_X4(b_l[p], bd + MAT_BYTES);
            }
            #pragma unroll
            for (int mt = 0; mt < 4; mt++)
                #pragma unroll
                for (int nt = 0; nt < 4; nt++) {
                    uint32_t bh0 = b_h[nt >> 1][(nt & 1) * 2];
                    uint32_t bh1 = b_h[nt >> 1][(nt & 1) * 2 + 1];
                    mma16<FP16>(acc[mt][nt], a_h[mt], bh0, bh1);
                    if (PASSES == 3) {
                        uint32_t bl0 = b_l[nt >> 1][(nt & 1) * 2];
                        uint32_t bl1 = b_l[nt >> 1][(nt & 1) * 2 + 1];
                        mma16<FP16>(acc[mt][nt], a_h[mt], bl0, bl1);
                    }
                    mma16<FP16>(acc[mt][nt], a_l[mt], bh0, bh1);
                }
        }
    }

    // ---- epilogue ----
    #pragma unroll
    for (int mt = 0; mt < 4; mt++) {
        #pragma unroll
        for (int nt = 0; nt < 4; nt++) {
            int mbase = m0 + wm * 64 + mt * 16 + (lane >> 2);
            int n = n0 + wn * 32 + nt * 8 + (lane & 3) * 2;
            #pragma unroll
            for (int hf = 0; hf < 2; hf++) {
                int mm = mbase + hf * 8;
                float vx = acc[mt][nt][hf * 2 + 0];
                float vy = acc[mt][nt][hf * 2 + 1];
                long idx = zC + (long)mm * ldc + n;
                if (EPI >= 2) { vx += bias[n]; vy += bias[n + 1]; }
                if (EPI == 2) { vx = fmaxf(vx, 0.f); vy = fmaxf(vy, 0.f); }
                if (EPI == 1 || EPI == 3) {
                    float2 old = *(const float2*)(Cf + idx);
                    vx += old.x; vy += old.y;
                }
                if (F32OUT) {
                    float2 o; o.x = vx; o.y = vy;
                    *(float2*)(Cf + idx) = o;
                }
                if (SPLITOUT) {
                    bf16 hx, lx, hy, ly;
                    split1(vx, hx, lx); split1(vy, hy, ly);
                    bf162 hv; hv.x = hx; hv.y = hy;
                    bf162 lv; lv.x = lx; lv.y = ly;
                    *(bf162*)(Ch + idx) = hv;
                    *(bf162*)(Cl + idx) = lv;
                }
            }
        }
    }
}

// ---------------- host ----------------
template<int EPI, bool F32O, bool SPL, bool CSKIP = false, bool CK = false,
         int PASSES = 3, bool FP16 = false>
static void launch_mma(dim3 grid, const void* Ah, const void* Al,
                       const void* Bh, const void* Bl,
                       float* Cf, bf16* Ch, bf16* Cl, const float* bias,
                       int K, int lda, int ldb, int ldc,
                       long bsA = 0, long bsB = 0, long bsC = 0) {
    cudaFuncSetAttribute(mma_gemm<EPI, F32O, SPL, CSKIP, CK, PASSES, FP16>,
                         cudaFuncAttributeMaxDynamicSharedMemorySize, SMEM_TOT);
    mma_gemm<EPI, F32O, SPL, CSKIP, CK, PASSES, FP16><<<grid, 256, SMEM_TOT>>>(
        (const bf16*)Ah, (const bf16*)Al, (const bf16*)Bh, (const bf16*)Bl,
        Cf, Ch, Cl, bias, K, lda, ldb, ldc, bsA, bsB, bsC);
}

extern "C" void kernel_launch(void* const* d_in, const int* in_sizes, int n_in,
                              void* d_out, int out_size) {
    const int*   tokens    = (const int*)  d_in[0];
    const float* embedding = (const float*)d_in[1];
    const float* qkv_w     = (const float*)d_in[2];
    const float* o_w       = (const float*)d_in[3];
    const float* up_w      = (const float*)d_in[4];
    const float* up_b      = (const float*)d_in[5];
    const float* down_w    = (const float*)d_in[6];
    const float* down_b    = (const float*)d_in[7];
    const float* unemb_w   = (const float*)d_in[8];
    const float* unemb_b   = (const float*)d_in[9];
    float* logits = (float*)d_out;

    float *x, *qkv, *sc;
    bf16 *xh, *xl, *qh, *ql, *sh, *sl, *vTh, *vTl, *oh, *ol, *hh, *hl;
    bf16 *qkvTh, *qkvTl, *oTh, *oTl, *upTh, *upTl, *dnTh, *dnTl;
    __half *unT16, *xh16, *xl16;
    cudaGetSymbolAddress((void**)&x, g_x);
    cudaGetSymbolAddress((void**)&qkv, g_qkv);
    cudaGetSymbolAddress((void**)&sc, g_scores);
    cudaGetSymbolAddress((void**)&xh, g_xh);   cudaGetSymbolAddress((void**)&xl, g_xl);
    cudaGetSymbolAddress((void**)&qh, g_qkvh); cudaGetSymbolAddress((void**)&ql, g_qkvl);
    cudaGetSymbolAddress((void**)&sh, g_sh);   cudaGetSymbolAddress((void**)&sl, g_sl);
    cudaGetSymbolAddress((void**)&vTh, g_vTh); cudaGetSymbolAddress((void**)&vTl, g_vTl);
    cudaGetSymbolAddress((void**)&oh, g_oh);   cudaGetSymbolAddress((void**)&ol, g_ol);
    cudaGetSymbolAddress((void**)&hh, g_hh);   cudaGetSymbolAddress((void**)&hl, g_hl);
    cudaGetSymbolAddress((void**)&qkvTh, g_qkvTh); cudaGetSymbolAddress((void**)&qkvTl, g_qkvTl);
    cudaGetSymbolAddress((void**)&oTh, g_oTh);     cudaGetSymbolAddress((void**)&oTl, g_oTl);
    cudaGetSymbolAddress((void**)&upTh, g_upTh);   cudaGetSymbolAddress((void**)&upTl, g_upTl);
    cudaGetSymbolAddress((void**)&dnTh, g_dnTh);   cudaGetSymbolAddress((void**)&dnTl, g_dnTl);
    cudaGetSymbolAddress((void**)&unT16, g_unT16);
    cudaGetSymbolAddress((void**)&xh16, g_xh16);   cudaGetSymbolAddress((void**)&xl16, g_xl16);

    const float scale = 1.0f / sqrtf((float)KDIM);
    dim3 tb(32, 8);

    transpose_split<<<dim3(3 * KDIM / 32, HDIM / 32, LAYERS), tb>>>(
        qkv_w, qkvTh, qkvTl, HDIM, 3 * KDIM, (long)HDIM * 3 * KDIM, (long)HDIM * 3 * KDIM);
    transpose_split<<<dim3(HDIM / 32, KDIM / 32, LAYERS), tb>>>(
        o_w, oTh, oTl, KDIM, HDIM, (long)KDIM * HDIM, (long)KDIM * HDIM);
    transpose_split<<<dim3(IDIM / 32, HDIM / 32, LAYERS), tb>>>(
        up_w, upTh, upTl, HDIM, IDIM, (long)HDIM * IDIM, (long)HDIM * IDIM);
    transpose_split<<<dim3(HDIM / 32, IDIM / 32, LAYERS), tb>>>(
        down_w, dnTh, dnTl, IDIM, HDIM, (long)IDIM * HDIM, (long)IDIM * HDIM);
    transpose_f16<<<dim3(VOCAB / 32, HDIM / 32), tb>>>(unemb_w, unT16, HDIM, VOCAB);

    embed_split<<<MTOK, 256>>>(tokens, embedding, x, xh, xl);

    for (int l = 0; l < LAYERS; l++) {
        bf16* wqh = qkvTh + (long)l * 3 * KDIM * HDIM;
        bf16* wql = qkvTl + (long)l * 3 * KDIM * HDIM;
        bf16* woh = oTh   + (long)l * HDIM * KDIM;
        bf16* wol = oTl   + (long)l * HDIM * KDIM;
        bf16* wuh = upTh  + (long)l * IDIM * HDIM;
        bf16* wul = upTl  + (long)l * IDIM * HDIM;
        bf16* wdh = dnTh  + (long)l * HDIM * IDIM;
        bf16* wdl = dnTl  + (long)l * HDIM * IDIM;
        const float* bu = up_b   + (long)l * IDIM;
        const float* bd = down_b + (long)l * HDIM;

        // qkv = x @ Wqkv -> fp32 (for V transpose) + split
        launch_mma<0, true, true>(dim3(3 * KDIM / 128, MTOK / 128, 1),
            xh, xl, wqh, wql, qkv, qh, ql, nullptr, HDIM, HDIM, HDIM, 3 * KDIM);

        transpose_split<<<dim3(KDIM / 32, SEQ / 32, BATCH), tb>>>(
            qkv + 2 * KDIM, vTh, vTl, SEQ, 3 * KDIM,
            (long)SEQ * 3 * KDIM, (long)KDIM * SEQ);

        // scores = Q @ K^T per batch (skip upper-triangle blocks)
        launch_mma<0, true, false, true, false>(dim3(SEQ / 128, SEQ / 128, BATCH),
            qh, ql, qh + KDIM, ql + KDIM, sc, nullptr, nullptr, nullptr,
            KDIM, 3 * KDIM, 3 * KDIM, SEQ,
            (long)SEQ * 3 * KDIM, (long)SEQ * 3 * KDIM, (long)SEQ * SEQ);

        softmax_split<<<BATCH * SEQ, 256>>>(sc, sh, sl, scale);

        // o = attn @ V per batch (K loop truncated at diagonal)
        launch_mma<0, false, true, false, true>(dim3(KDIM / 128, SEQ / 128, BATCH),
            sh, sl, vTh, vTl, nullptr, oh, ol, nullptr,
            SEQ, SEQ, SEQ, KDIM,
            (long)SEQ * SEQ, (long)KDIM * SEQ, (long)SEQ * KDIM);

        // x += o @ Wo
        launch_mma<1, true, true>(dim3(HDIM / 128, MTOK / 128, 1),
            oh, ol, woh, wol, x, xh, xl, nullptr, KDIM, KDIM, KDIM, HDIM);

        // h = relu(x @ Wu + bu)
        launch_mma<2, false, true>(dim3(IDIM / 128, MTOK / 128, 1),
            xh, xl, wuh, wul, nullptr, hh, hl, bu, HDIM, HDIM, HDIM, IDIM);

        // x += h @ Wd + bd
        launch_mma<3, true, true>(dim3(HDIM / 128, MTOK / 128, 1),
            hh, hl, wdh, wdl, x, xh, xl, bd, IDIM, IDIM, IDIM, HDIM);
    }

    // unembed: fp16 2-pass (A split hi/lo fp16, B single fp16)
    split_f16<<<MTOK, 256>>>(x, xh16, xl16);
    launch_mma<4, true, false, false, false, 2, true>(
        dim3(VOCAB / 128, MTOK / 128, 1),
        xh16, xl16, unT16, unT16, logits, nullptr, nullptr, unemb_b,
        HDIM, HDIM, HDIM, VOCAB);
}

// round 7
// speedup vs baseline: 1.6700x; 1.0422x over previous
#include <cuda_runtime.h>
#include <cuda_bf16.h>
#include <cuda_fp16.h>
#include <math.h>
#include <stdint.h>

#define LAYERS 8
#define HDIM   1024
#define KDIM   1024
#define IDIM   4096
#define VOCAB  32000
#define BATCH  2
#define SEQ    2048
#define MTOK   (BATCH * SEQ)

typedef __nv_bfloat16 bf16;
typedef __nv_bfloat162 bf162;

// ---------------- scratch (device globals) ----------------
__device__ float g_x[(long)MTOK * HDIM];
__device__ float g_qkv[(long)MTOK * 3 * KDIM];
__device__ float g_scores[(long)BATCH * SEQ * SEQ];
__device__ bf16 g_xh[(long)MTOK * HDIM],      g_xl[(long)MTOK * HDIM];
__device__ bf16 g_qkvh[(long)MTOK * 3 * KDIM], g_qkvl[(long)MTOK * 3 * KDIM];
__device__ bf16 g_sh[(long)BATCH * SEQ * SEQ], g_sl[(long)BATCH * SEQ * SEQ];
__device__ bf16 g_vTh[(long)BATCH * KDIM * SEQ], g_vTl[(long)BATCH * KDIM * SEQ];
__device__ bf16 g_oh[(long)MTOK * KDIM],      g_ol[(long)MTOK * KDIM];
__device__ bf16 g_hh[(long)MTOK * IDIM],      g_hl[(long)MTOK * IDIM];
__device__ bf16 g_qkvTh[(long)LAYERS * 3 * KDIM * HDIM], g_qkvTl[(long)LAYERS * 3 * KDIM * HDIM];
__device__ bf16 g_oTh[(long)LAYERS * HDIM * KDIM],       g_oTl[(long)LAYERS * HDIM * KDIM];
__device__ bf16 g_upTh[(long)LAYERS * IDIM * HDIM],      g_upTl[(long)LAYERS * IDIM * HDIM];
__device__ bf16 g_dnTh[(long)LAYERS * HDIM * IDIM],      g_dnTl[(long)LAYERS * HDIM * IDIM];
// fp16 unembed path
__device__ __half g_unT16[(long)VOCAB * HDIM];
__device__ __half g_xh16[(long)MTOK * HDIM], g_xl16[(long)MTOK * HDIM];

// ---------------- helpers ----------------
__device__ __forceinline__ uint32_t smem_u32(const void* p) {
    uint32_t a;
    asm("{ .reg .u64 t; cvta.to.shared.u64 t, %1; cvt.u32.u64 %0, t; }" : "=r"(a) : "l"(p));
    return a;
}
__device__ __forceinline__ void split1(float v, bf16& h, bf16& l) {
    h = __float2bfloat16_rn(v);
    l = __float2bfloat16_rn(v - __bfloat162float(h));
}

#define CP_ASYNC16(dst, src) \
    asm volatile("cp.async.cg.shared.global [%0], [%1], 16;" :: "r"(dst), "l"(src) : "memory")
#define CP_COMMIT() asm volatile("cp.async.commit_group;" ::: "memory")
#define CP_WAIT1()  asm volatile("cp.async.wait_group 1;" ::: "memory")

#define LDSM_X4(r, a)                                                        \
    asm volatile("ldmatrix.sync.aligned.m8n8.x4.shared.b16 {%0,%1,%2,%3}, [%4];" \
        : "=r"((r)[0]), "=r"((r)[1]), "=r"((r)[2]), "=r"((r)[3]) : "r"(a))

template<bool FP16>
__device__ __forceinline__ void mma16(float* c, const uint32_t* a,
                                      uint32_t b0, uint32_t b1) {
    if (FP16)
        asm volatile(
            "mma.sync.aligned.m16n8k16.row.col.f32.f16.f16.f32 "
            "{%0,%1,%2,%3}, {%4,%5,%6,%7}, {%8,%9}, {%0,%1,%2,%3};"
            : "+f"(c[0]), "+f"(c[1]), "+f"(c[2]), "+f"(c[3])
            : "r"(a[0]), "r"(a[1]), "r"(a[2]), "r"(a[3]), "r"(b0), "r"(b1));
    else
        asm volatile(
            "mma.sync.aligned.m16n8k16.row.col.f32.bf16.bf16.f32 "
            "{%0,%1,%2,%3}, {%4,%5,%6,%7}, {%8,%9}, {%0,%1,%2,%3};"
            : "+f"(c[0]), "+f"(c[1]), "+f"(c[2]), "+f"(c[3])
            : "r"(a[0]), "r"(a[1]), "r"(a[2]), "r"(a[3]), "r"(b0), "r"(b1));
}

// ---------------- embed (+split) ----------------
__global__ void embed_split(const int* __restrict__ tokens, const float* __restrict__ emb,
                            float* __restrict__ x, bf16* __restrict__ xh, bf16* __restrict__ xl) {
    int i = blockIdx.x;
    int tok = tokens[i];
    const float4* src = (const float4*)(emb + (long)tok * HDIM);
    float4* dst = (float4*)(x + (long)i * HDIM);
    for (int c = threadIdx.x; c < HDIM / 4; c += blockDim.x) {
        float4 v = src[c];
        dst[c] = v;
        bf16 h0, l0, h1, l1, h2, l2, h3, l3;
        split1(v.x, h0, l0); split1(v.y, h1, l1);
        split1(v.z, h2, l2); split1(v.w, h3, l3);
        long base = (long)i * HDIM + c * 4;
        bf162 a; a.x = h0; a.y = h1;
        bf162 b; b.x = h2; b.y = h3;
        *(bf162*)(xh + base) = a; *(bf162*)(xh + base + 2) = b;
        a.x = l0; a.y = l1; b.x = l2; b.y = l3;
        *(bf162*)(xl + base) = a; *(bf162*)(xl + base + 2) = b;
    }
}

// ---------------- transpose + split (bf16 hi/lo) ----------------
__global__ void transpose_split(const float* __restrict__ src,
                                bf16* __restrict__ dh, bf16* __restrict__ dl,
                                int R, int lds, long sbatch, long dbatch) {
    __shared__ float t[32][33];
    src += (long)blockIdx.z * sbatch;
    dh  += (long)blockIdx.z * dbatch;
    dl  += (long)blockIdx.z * dbatch;
    int c0 = blockIdx.x << 5, r0 = blockIdx.y << 5;
    int x = threadIdx.x, y = threadIdx.y;
    #pragma unroll
    for (int i = y; i < 32; i += 8)
        t[i][x] = src[(long)(r0 + i) * lds + c0 + x];
    __syncthreads();
    #pragma unroll
    for (int j = y; j < 32; j += 8) {
        float v = t[x][j];
        bf16 h, l; split1(v, h, l);
        long idx = (long)(c0 + j) * R + r0 + x;
        dh[idx] = h; dl[idx] = l;
    }
}

// ---------------- transpose -> single fp16 ----------------
__global__ void transpose_f16(const float* __restrict__ src, __half* __restrict__ dst,
                              int R, int lds) {
    __shared__ float t[32][33];
    int c0 = blockIdx.x << 5, r0 = blockIdx.y << 5;
    int x = threadIdx.x, y = threadIdx.y;
    #pragma unroll
    for (int i = y; i < 32; i += 8)
        t[i][x] = src[(long)(r0 + i) * lds + c0 + x];
    __syncthreads();
    #pragma unroll
    for (int j = y; j < 32; j += 8)
        dst[(long)(c0 + j) * R + r0 + x] = __float2half_rn(t[x][j]);
}

// ---------------- fp32 -> fp16 hi/lo split ----------------
__global__ void split_f16(const float* __restrict__ src,
                          __half* __restrict__ dh, __half* __restrict__ dl) {
    int i = blockIdx.x;
    const float4* s = (const float4*)(src + (long)i * HDIM);
    for (int c = threadIdx.x; c < HDIM / 4; c += blockDim.x) {
        float4 v = s[c];
        long base = (long)i * HDIM + c * 4;
        float vv[4] = { v.x, v.y, v.z, v.w };
        #pragma unroll
        for (int q = 0; q < 4; q++) {
            __half h = __float2half_rn(vv[q]);
            __half l = __float2half_rn(vv[q] - __half2float(h));
            dh[base + q] = h; dl[base + q] = l;
        }
    }
}

// ---------------- causal softmax -> split bf16 ----------------
__global__ void softmax_split(float* __restrict__ sc, bf16* __restrict__ sh,
                              bf16* __restrict__ sl, float scale) {
    int row = blockIdx.x;
    int s = row & (SEQ - 1);
    float* p = sc + (long)row * SEQ;
    bf16* ph = sh + (long)row * SEQ;
    bf16* pl = sl + (long)row * SEQ;
    int tid = threadIdx.x;
    __shared__ float red[256];

    float m = -INFINITY;
    for (int t = tid; t <= s; t += blockDim.x) m = fmaxf(m, p[t] * scale);
    red[tid] = m; __syncthreads();
    for (int o = 128; o > 0; o >>= 1) {
        if (tid < o) red[tid] = fmaxf(red[tid], red[tid + o]);
        __syncthreads();
    }
    m = red[0]; __syncthreads();

    float sum = 0.f;
    for (int t = tid; t <= s; t += blockDim.x) {
        float e = __expf(p[t] * scale - m);
        p[t] = e;
        sum += e;
    }
    red[tid] = sum; __syncthreads();
    for (int o = 128; o > 0; o >>= 1) {
        if (tid < o) red[tid] += red[tid + o];
        __syncthreads();
    }
    float inv = 1.f / red[0];
    const bf16 z = __float2bfloat16(0.f);
    for (int t = tid; t <= s; t += blockDim.x) {
        bf16 h, l; split1(p[t] * inv, h, l);
        ph[t] = h; pl[t] = l;
    }
    for (int t = s + 1 + tid; t < SEQ; t += blockDim.x) { ph[t] = z; pl[t] = z; }
}

// ---------------- HMMA GEMM: C[M,N] = A[M,K] @ B[N,K]^T --------------------
// CTA tile 128x256x32, 256 threads, 8 warps (2 M x 4 N), 64x64 warp tiles.
// PASSES=3: Ah*Bh + Ah*Bl + Al*Bh (bf16). PASSES=2: Ah*Bh + Al*Bh (B single fp16).
// EPI: 0 none, 1 +=Cf, 2 relu(+bias), 3 +bias+Cf, 4 +bias
// CSKIP: skip blocks with n0 > m0+127.  CK: truncate K loop at m0+128.
#define DEPTH     3
#define MAT_A     10240u                  // 128 rows * 80B
#define MAT_B     20480u                  // 256 rows * 80B
#define STG_BYTES 61440u                  // 2*MAT_A + 2*MAT_B
#define SMEM_TOT  (DEPTH * STG_BYTES)     // 184320

template<int EPI, bool F32OUT, bool SPLITOUT, bool CSKIP, bool CK, int PASSES, bool FP16>
__global__ __launch_bounds__(256, 1)
void mma_gemm(const bf16* __restrict__ Ah, const bf16* __restrict__ Al,
              const bf16* __restrict__ Bh, const bf16* __restrict__ Bl,
              float* __restrict__ Cf, bf16* __restrict__ Ch, bf16* __restrict__ Cl,
              const float* __restrict__ bias,
              int K, int lda, int ldb, int ldc,
              long bsA, long bsB, long bsC) {
    const int m0 = blockIdx.y << 7;          // 128-row M tile
    const int n0 = blockIdx.x << 8;          // 256-col N tile
    if (CSKIP && n0 > m0 + 127) return;

    const long zA = (long)blockIdx.z * bsA;
    const long zB = (long)blockIdx.z * bsB;
    const long zC = (long)blockIdx.z * bsC;

    extern __shared__ char smem[];
    const uint32_t sbase = smem_u32(smem);
    const int tid = threadIdx.x;
    const int lane = tid & 31, wid = tid >> 5;
    const int wm = wid & 1, wn = wid >> 1;   // 2 x 4 warp grid
    int NK = K >> 5;
    if (CK) { int nke = (m0 + 128) >> 5; NK = (nke < NK) ? nke : NK; }
    constexpr int NROWI = (PASSES == 3) ? 12 : 8;   // 64-row groups per stage

    const bf16* gm[4] = { Ah + zA + (long)m0 * lda, Al + zA + (long)m0 * lda,
                          Bh + zB + (long)n0 * ldb, Bl + zB + (long)n0 * ldb };
    const int  ldm[4]  = { lda, lda, ldb, ldb };
    const uint32_t moff[4] = { 0u, MAT_A, 2u * MAT_A, 2u * MAT_A + MAT_B };
    const int rgrp = tid >> 2;      // 0..63 row within 64-row group
    const int atom = tid & 3;       // 16B chunk

    float acc[4][8][4];
    #pragma unroll
    for (int a = 0; a < 4; a++)
        #pragma unroll
        for (int b = 0; b < 8; b++)
            #pragma unroll
            for (int c = 0; c < 4; c++) acc[a][b][c] = 0.f;

    // region starts (in 64-row groups): A_h i=0,1  A_l i=2,3  B_h i=4..7  B_l i=8..11
    #define LOAD_STAGE(kt, slot) do {                                          \
        uint32_t st_ = sbase + (slot) * STG_BYTES;                             \
        _Pragma("unroll")                                                      \
        for (int i = 0; i < NROWI; i++) {                                      \
            const int mat = (i < 2) ? 0 : (i < 4) ? 1 : (i < 8) ? 2 : 3;       \
            const int lr  = (i - ((mat == 0) ? 0 : (mat == 1) ? 2 : (mat == 2) ? 4 : 8)) * 64 + rgrp; \
            const bf16* g = gm[mat] + (long)lr * ldm[mat] + ((kt) << 5) + (atom << 3); \
            CP_ASYNC16(st_ + moff[mat] + (uint32_t)lr * 80u + (atom << 4), g); \
        }                                                                      \
        CP_COMMIT();                                                           \
    } while (0)

    LOAD_STAGE(0, 0);
    LOAD_STAGE(1, 1);

    for (int kt = 0; kt < NK; kt++) {
        CP_WAIT1();
        __syncthreads();
        if (kt + 2 < NK) { LOAD_STAGE(kt + 2, (kt + 2) % DEPTH); }
        else             { CP_COMMIT(); }

        uint32_t st = sbase + (kt % DEPTH) * STG_BYTES;
        #pragma unroll
        for (int s = 0; s < 2; s++) {
            uint32_t a_h[4][4], a_l[4][4];
            #pragma unroll
            for (int mt = 0; mt < 4; mt++) {
                uint32_t ad = st + (uint32_t)(wm * 64 + mt * 16 + (lane & 15)) * 80u
                              + s * 32 + ((lane >> 4) << 4);
                LDSM_X4(a_h[mt], ad);
                LDSM_X4(a_l[mt], ad + MAT_A);
            }
            #pragma unroll
            for (int p = 0; p < 4; p++) {
                uint32_t b_h[4], b_l[4];
                uint32_t bd = st + 2u * MAT_A
                              + (uint32_t)(wn * 64 + p * 16 + ((lane >> 4) << 3) + (lane & 7)) * 80u
                              + s * 32 + (((lane >> 3) & 1) << 4);
                LDSM_X4(b_h, bd);
                if (PASSES == 3) LDSM_X4(b_l, bd + MAT_B);
                #pragma unroll
                for (int q = 0; q < 2; q++) {
                    const int nt = p * 2 + q;
                    uint32_t bh0 = b_h[q * 2], bh1 = b_h[q * 2 + 1];
                    #pragma unroll
                    for (int mt = 0; mt < 4; mt++) {
                        mma16<FP16>(acc[mt][nt], a_h[mt], bh0, bh1);
                        if (PASSES == 3)
                            mma16<FP16>(acc[mt][nt], a_h[mt], b_l[q * 2], b_l[q * 2 + 1]);
                        mma16<FP16>(acc[mt][nt], a_l[mt], bh0, bh1);
                    }
                }
            }
        }
    }

    // ---- epilogue ----
    #pragma unroll
    for (int mt = 0; mt < 4; mt++) {
        #pragma unroll
        for (int nt = 0; nt < 8; nt++) {
            int mbase = m0 + wm * 64 + mt * 16 + (lane >> 2);
            int n = n0 + wn * 64 + nt * 8 + (lane & 3) * 2;
            #pragma unroll
            for (int hf = 0; hf < 2; hf++) {
                int mm = mbase + hf * 8;
                float vx = acc[mt][nt][hf * 2 + 0];
                float vy = acc[mt][nt][hf * 2 + 1];
                long idx = zC + (long)mm * ldc + n;
                if (EPI >= 2) { vx += bias[n]; vy += bias[n + 1]; }
                if (EPI == 2) { vx = fmaxf(vx, 0.f); vy = fmaxf(vy, 0.f); }
                if (EPI == 1 || EPI == 3) {
                    float2 old = *(const float2*)(Cf + idx);
                    vx += old.x; vy += old.y;
                }
                if (F32OUT) {
                    float2 o; o.x = vx; o.y = vy;
                    *(float2*)(Cf + idx) = o;
                }
                if (SPLITOUT) {
                    bf16 hx, lx, hy, ly;
                    split1(vx, hx, lx); split1(vy, hy, ly);
                    bf162 hv; hv.x = hx; hv.y = hy;
                    bf162 lv; lv.x = lx; lv.y = ly;
                    *(bf162*)(Ch + idx) = hv;
                    *(bf162*)(Cl + idx) = lv;
                }
            }
        }
    }
}

// ---------------- host ----------------
template<int EPI, bool F32O, bool SPL, bool CSKIP = false, bool CK = false,
         int PASSES = 3, bool FP16 = false>
static void launch_mma(dim3 grid, const void* Ah, const void* Al,
                       const void* Bh, const void* Bl,
                       float* Cf, bf16* Ch, bf16* Cl, const float* bias,
                       int K, int lda, int ldb, int ldc,
                       long bsA = 0, long bsB = 0, long bsC = 0) {
    cudaFuncSetAttribute(mma_gemm<EPI, F32O, SPL, CSKIP, CK, PASSES, FP16>,
                         cudaFuncAttributeMaxDynamicSharedMemorySize, SMEM_TOT);
    mma_gemm<EPI, F32O, SPL, CSKIP, CK, PASSES, FP16><<<grid, 256, SMEM_TOT>>>(
        (const bf16*)Ah, (const bf16*)Al, (const bf16*)Bh, (const bf16*)Bl,
        Cf, Ch, Cl, bias, K, lda, ldb, ldc, bsA, bsB, bsC);
}

extern "C" void kernel_launch(void* const* d_in, const int* in_sizes, int n_in,
                              void* d_out, int out_size) {
    const int*   tokens    = (const int*)  d_in[0];
    const float* embedding = (const float*)d_in[1];
    const float* qkv_w     = (const float*)d_in[2];
    const float* o_w       = (const float*)d_in[3];
    const float* up_w      = (const float*)d_in[4];
    const float* up_b      = (const float*)d_in[5];
    const float* down_w    = (const float*)d_in[6];
    const float* down_b    = (const float*)d_in[7];
    const float* unemb_w   = (const float*)d_in[8];
    const float* unemb_b   = (const float*)d_in[9];
    float* logits = (float*)d_out;

    float *x, *qkv, *sc;
    bf16 *xh, *xl, *qh, *ql, *sh, *sl, *vTh, *vTl, *oh, *ol, *hh, *hl;
    bf16 *qkvTh, *qkvTl, *oTh, *oTl, *upTh, *upTl, *dnTh, *dnTl;
    __half *unT16, *xh16, *xl16;
    cudaGetSymbolAddress((void**)&x, g_x);
    cudaGetSymbolAddress((void**)&qkv, g_qkv);
    cudaGetSymbolAddress((void**)&sc, g_scores);
    cudaGetSymbolAddress((void**)&xh, g_xh);   cudaGetSymbolAddress((void**)&xl, g_xl);
    cudaGetSymbolAddress((void**)&qh, g_qkvh); cudaGetSymbolAddress((void**)&ql, g_qkvl);
    cudaGetSymbolAddress((void**)&sh, g_sh);   cudaGetSymbolAddress((void**)&sl, g_sl);
    cudaGetSymbolAddress((void**)&vTh, g_vTh); cudaGetSymbolAddress((void**)&vTl, g_vTl);
    cudaGetSymbolAddress((void**)&oh, g_oh);   cudaGetSymbolAddress((void**)&ol, g_ol);
    cudaGetSymbolAddress((void**)&hh, g_hh);   cudaGetSymbolAddress((void**)&hl, g_hl);
    cudaGetSymbolAddress((void**)&qkvTh, g_qkvTh); cudaGetSymbolAddress((void**)&qkvTl, g_qkvTl);
    cudaGetSymbolAddress((void**)&oTh, g_oTh);     cudaGetSymbolAddress((void**)&oTl, g_oTl);
    cudaGetSymbolAddress((void**)&upTh, g_upTh);   cudaGetSymbolAddress((void**)&upTl, g_upTl);
    cudaGetSymbolAddress((void**)&dnTh, g_dnTh);   cudaGetSymbolAddress((void**)&dnTl, g_dnTl);
    cudaGetSymbolAddress((void**)&unT16, g_unT16);
    cudaGetSymbolAddress((void**)&xh16, g_xh16);   cudaGetSymbolAddress((void**)&xl16, g_xl16);

    const float scale = 1.0f / sqrtf((float)KDIM);
    dim3 tb(32, 8);

    transpose_split<<<dim3(3 * KDIM / 32, HDIM / 32, LAYERS), tb>>>(
        qkv_w, qkvTh, qkvTl, HDIM, 3 * KDIM, (long)HDIM * 3 * KDIM, (long)HDIM * 3 * KDIM);
    transpose_split<<<dim3(HDIM / 32, KDIM / 32, LAYERS), tb>>>(
        o_w, oTh, oTl, KDIM, HDIM, (long)KDIM * HDIM, (long)KDIM * HDIM);
    transpose_split<<<dim3(IDIM / 32, HDIM / 32, LAYERS), tb>>>(
        up_w, upTh, upTl, HDIM, IDIM, (long)HDIM * IDIM, (long)HDIM * IDIM);
    transpose_split<<<dim3(HDIM / 32, IDIM / 32, LAYERS), tb>>>(
        down_w, dnTh, dnTl, IDIM, HDIM, (long)IDIM * HDIM, (long)IDIM * HDIM);
    transpose_f16<<<dim3(VOCAB / 32, HDIM / 32), tb>>>(unemb_w, unT16, HDIM, VOCAB);

    embed_split<<<MTOK, 256>>>(tokens, embedding, x, xh, xl);

    for (int l = 0; l < LAYERS; l++) {
        bf16* wqh = qkvTh + (long)l * 3 * KDIM * HDIM;
        bf16* wql = qkvTl + (long)l * 3 * KDIM * HDIM;
        bf16* woh = oTh   + (long)l * HDIM * KDIM;
        bf16* wol = oTl   + (long)l * HDIM * KDIM;
        bf16* wuh = upTh  + (long)l * IDIM * HDIM;
        bf16* wul = upTl  + (long)l * IDIM * HDIM;
        bf16* wdh = dnTh  + (long)l * HDIM * IDIM;
        bf16* wdl = dnTl  + (long)l * HDIM * IDIM;
        const float* bu = up_b   + (long)l * IDIM;
        const float* bd = down_b + (long)l * HDIM;

        // qkv = x @ Wqkv -> fp32 (for V transpose) + split
        launch_mma<0, true, true>(dim3(3 * KDIM / 256, MTOK / 128, 1),
            xh, xl, wqh, wql, qkv, qh, ql, nullptr, HDIM, HDIM, HDIM, 3 * KDIM);

        transpose_split<<<dim3(KDIM / 32, SEQ / 32, BATCH), tb>>>(
            qkv + 2 * KDIM, vTh, vTl, SEQ, 3 * KDIM,
            (long)SEQ * 3 * KDIM, (long)KDIM * SEQ);

        // scores = Q @ K^T per batch (skip blocks fully above diagonal)
        launch_mma<0, true, false, true, false>(dim3(SEQ / 256, SEQ / 128, BATCH),
            qh, ql, qh + KDIM, ql + KDIM, sc, nullptr, nullptr, nullptr,
            KDIM, 3 * KDIM, 3 * KDIM, SEQ,
            (long)SEQ * 3 * KDIM, (long)SEQ * 3 * KDIM, (long)SEQ * SEQ);

        softmax_split<<<BATCH * SEQ, 256>>>(sc, sh, sl, scale);

        // o = attn @ V per batch (K loop truncated at diagonal)
        launch_mma<0, false, true, false, true>(dim3(KDIM / 256, SEQ / 128, BATCH),
            sh, sl, vTh, vTl, nullptr, oh, ol, nullptr,
            SEQ, SEQ, SEQ, KDIM,
            (long)SEQ * SEQ, (long)KDIM * SEQ, (long)SEQ * KDIM);

        // x += o @ Wo
        launch_mma<1, true, true>(dim3(HDIM / 256, MTOK / 128, 1),
            oh, ol, woh, wol, x, xh, xl, nullptr, KDIM, KDIM, KDIM, HDIM);

        // h = relu(x @ Wu + bu)
        launch_mma<2, false, true>(dim3(IDIM / 256, MTOK / 128, 1),
            xh, xl, wuh, wul, nullptr, hh, hl, bu, HDIM, HDIM, HDIM, IDIM);

        // x += h @ Wd + bd
        launch_mma<3, true, true>(dim3(HDIM / 256, MTOK / 128, 1),
            hh, hl, wdh, wdl, x, xh, xl, bd, IDIM, IDIM, IDIM, HDIM);
    }

    // unembed: fp16 2-pass (A split hi/lo fp16, B single fp16)
    split_f16<<<MTOK, 256>>>(x, xh16, xl16);
    launch_mma<4, true, false, false, false, 2, true>(
        dim3(VOCAB / 256, MTOK / 128, 1),
        xh16, xl16, unT16, unT16, logits, nullptr, nullptr, unemb_b,
        HDIM, HDIM, HDIM, VOCAB);
}